// round 2
// baseline (speedup 1.0000x reference)
#include <cuda_runtime.h>

// harmonicLoss: [32, 516, 2048] fp32 logits -> scalar
//   loss     = mean_{b,s}( lse_v x[b,:,s] - x[b,tgt,s] )
//   pred     = argmax_v( x[b,v,s] - lse_s x[b,v,:] )   (softmax over seq axis, argmax over v)
//   result   = loss * (1 + mean(mask(pred, tgt)))

namespace {
constexpr int NB = 32;
constexpr int NV = 516;
constexpr int NS = 2048;
constexpr int P2_BLOCKS = 128;   // 32 b * 4 s-chunks of 512
}

__device__ float  g_rowlse[NB * NV];   // log sum_s exp(x[b,v,:])
__device__ float2 g_part[P2_BLOCKS];   // (sum_nll, sum_mask) per pass-2 block

// ---------------------------------------------------------------------------
// Pass 1: one block per (b,v) row of 2048 contiguous floats.
// ---------------------------------------------------------------------------
__global__ void __launch_bounds__(256) k_rowlse(const float* __restrict__ x) {
    const float4* p = reinterpret_cast<const float4*>(x + (size_t)blockIdx.x * NS);
    int t = threadIdx.x;
    float4 a = p[t];
    float4 b = p[t + 256];
    float s = __expf(a.x) + __expf(a.y) + __expf(a.z) + __expf(a.w)
            + __expf(b.x) + __expf(b.y) + __expf(b.z) + __expf(b.w);
#pragma unroll
    for (int o = 16; o > 0; o >>= 1) s += __shfl_down_sync(0xffffffffu, s, o);
    __shared__ float ws[8];
    if ((t & 31) == 0) ws[t >> 5] = s;
    __syncthreads();
    if (t == 0) {
        float tot = ws[0];
#pragma unroll
        for (int i = 1; i < 8; i++) tot += ws[i];
        g_rowlse[blockIdx.x] = __logf(tot);
    }
}

// ---------------------------------------------------------------------------
// Pass 2: one thread per (b,s) column; 512 threads/block, 128 blocks
// (single balanced wave). Streams 516 warp-coalesced loads per thread.
// ---------------------------------------------------------------------------
__global__ void __launch_bounds__(512) k_cols(
    const float* __restrict__ x,
    const int*   __restrict__ target,
    const int*   __restrict__ tt,
    const float* __restrict__ tvv,
    const float* __restrict__ coeff,
    const float* __restrict__ harm)
{
    int b = blockIdx.x >> 2;
    int s = ((blockIdx.x & 3) << 9) + threadIdx.x;

    __shared__ float sh_lse[NV];
    __shared__ float sh_tv[NV];
    __shared__ int   sh_tt[NV];
    for (int i = threadIdx.x; i < NV; i += 512) {
        sh_lse[i] = g_rowlse[b * NV + i];
        sh_tv[i]  = tvv[i];
        sh_tt[i]  = tt[i];
    }
    __syncthreads();

    const float* p = x + (size_t)b * NV * NS + s;
    int tgt = target[b * NS + s];

    float sumexp = 0.f;
    float best   = -3.4e38f;
    int   pred   = 0;
    float tval   = 0.f;
#pragma unroll 8
    for (int v = 0; v < NV; v++) {
        float xv = __ldg(p + (size_t)v * NS);
        sumexp += __expf(xv);
        float a = xv - sh_lse[v];
        if (a > best) { best = a; pred = v; }     // strict > keeps first index (jnp.argmax)
        tval = (v == tgt) ? xv : tval;             // branchless select
    }
    float nll = __logf(sumexp) - tval;

    // penalty mask
    int pt = sh_tt[pred], qt = sh_tt[tgt];
    float w;
    if (pt != qt) {
        w = __ldg(coeff + 0);
    } else {
        float d = fabsf(sh_tv[pred] - sh_tv[tgt]);   // integer-valued floats -> exact cmp
        if (pt == 0) {
            w = (d == 7.f) ? __ldg(harm + 0)
              : (d == 5.f) ? __ldg(harm + 1)
              : (d == 3.f) ? __ldg(harm + 2)
              : (d == 4.f) ? __ldg(harm + 3)
              : (d == 1.f) ? __ldg(harm + 4)
              : (d == 2.f) ? __ldg(harm + 5)
              :              __ldg(harm + 6);
        } else if (pt == 1) {
            w = __ldg(coeff + 1) * d * (1.f / 160.f);
        } else if (pt == 2) {
            w = __ldg(coeff + 2) * d * (1.f / 100.f);
        } else {
            w = __ldg(coeff + 3) * d * (1.f / 128.f);
        }
    }

    // block reduce (deterministic; no atomics)
#pragma unroll
    for (int o = 16; o > 0; o >>= 1) {
        nll += __shfl_down_sync(0xffffffffu, nll, o);
        w   += __shfl_down_sync(0xffffffffu, w,   o);
    }
    __shared__ float rn[16], rw[16];
    int wid = threadIdx.x >> 5;
    if ((threadIdx.x & 31) == 0) { rn[wid] = nll; rw[wid] = w; }
    __syncthreads();
    if (threadIdx.x == 0) {
        float an = 0.f, aw = 0.f;
#pragma unroll
        for (int i = 0; i < 16; i++) { an += rn[i]; aw += rw[i]; }
        g_part[blockIdx.x] = make_float2(an, aw);
    }
}

// ---------------------------------------------------------------------------
// Pass 3: fold 128 partials into the final scalar.
// ---------------------------------------------------------------------------
__global__ void __launch_bounds__(128) k_final(float* __restrict__ out) {
    float a = 0.f, w = 0.f;
    if (threadIdx.x < P2_BLOCKS) {
        float2 v = g_part[threadIdx.x];
        a = v.x; w = v.y;
    }
#pragma unroll
    for (int o = 16; o > 0; o >>= 1) {
        a += __shfl_down_sync(0xffffffffu, a, o);
        w += __shfl_down_sync(0xffffffffu, w, o);
    }
    __shared__ float ra[4], rw2[4];
    if ((threadIdx.x & 31) == 0) { ra[threadIdx.x >> 5] = a; rw2[threadIdx.x >> 5] = w; }
    __syncthreads();
    if (threadIdx.x == 0) {
        float ta = ra[0] + ra[1] + ra[2] + ra[3];
        float tw = rw2[0] + rw2[1] + rw2[2] + rw2[3];
        const float inv = 1.f / (float)(NB * NS);
        float loss = ta * inv;
        out[0] = loss * (1.f + tw * inv);
    }
}

extern "C" void kernel_launch(void* const* d_in, const int* in_sizes, int n_in,
                              void* d_out, int out_size) {
    const float* x      = (const float*)d_in[0];
    const int*   target = (const int*)  d_in[1];
    const int*   tt     = (const int*)  d_in[2];
    const float* tv     = (const float*)d_in[3];
    const float* coeff  = (const float*)d_in[4];
    const float* harm   = (const float*)d_in[5];

    k_rowlse<<<NB * NV, 256>>>(x);
    k_cols<<<P2_BLOCKS, 512>>>(x, target, tt, tv, coeff, harm);
    k_final<<<1, 128>>>((float*)d_out);
}

// round 3
// speedup vs baseline: 1.8088x; 1.8088x over previous
#include <cuda_runtime.h>

// harmonicLoss: [32, 516, 2048] fp32 logits -> scalar
//   loss     = mean_{b,s}( lse_v x[b,:,s] - x[b,tgt,s] )
//   pred     = argmax_v( x[b,v,s] - lse_s x[b,v,:] )   (softmax over seq axis, argmax over v)
//   result   = loss * (1 + mean(mask(pred, tgt)))

namespace {
constexpr int NB = 32;
constexpr int NV = 516;
constexpr int NS = 2048;
constexpr int P2_BLOCKS = 128;   // 32 b * 4 s-chunks of 512
constexpr int VCHUNK = 129;      // NV / 4
}

__device__ float  g_rowlse[NB * NV];   // log sum_s exp(x[b,v,:])
__device__ float2 g_part[P2_BLOCKS];   // (sum_nll, sum_mask) per pass-2 block

// ---------------------------------------------------------------------------
// Pass 1: one block per (b,v) row of 2048 contiguous floats.
// ---------------------------------------------------------------------------
__global__ void __launch_bounds__(256) k_rowlse(const float* __restrict__ x) {
    const float4* p = reinterpret_cast<const float4*>(x + (size_t)blockIdx.x * NS);
    int t = threadIdx.x;
    float4 a = p[t];
    float4 b = p[t + 256];
    float s = __expf(a.x) + __expf(a.y) + __expf(a.z) + __expf(a.w)
            + __expf(b.x) + __expf(b.y) + __expf(b.z) + __expf(b.w);
#pragma unroll
    for (int o = 16; o > 0; o >>= 1) s += __shfl_down_sync(0xffffffffu, s, o);
    __shared__ float ws[8];
    if ((t & 31) == 0) ws[t >> 5] = s;
    __syncthreads();
    if (t == 0) {
        float tot = ws[0];
#pragma unroll
        for (int i = 1; i < 8; i++) tot += ws[i];
        g_rowlse[blockIdx.x] = __logf(tot);
    }
}

// ---------------------------------------------------------------------------
// Pass 2 (v2): 128 blocks x 512 threads, single wave.
//   Each thread handles 4 adjacent columns (float4 loads) over a 129-wide
//   v-chunk; 4 warps per s-group cover the 4 chunks; partials combined in smem.
// ---------------------------------------------------------------------------
__global__ void __launch_bounds__(512) k_cols(
    const float* __restrict__ x,
    const int*   __restrict__ target,
    const int*   __restrict__ tt,
    const float* __restrict__ tvv,
    const float* __restrict__ coeff,
    const float* __restrict__ harm)
{
    const int b     = blockIdx.x >> 2;
    const int sbase = (blockIdx.x & 3) << 9;

    __shared__ float sh_lse[NV];
    __shared__ float p_sum [4][512];
    __shared__ float p_best[4][512];
    __shared__ int   p_pred[4][512];

    for (int i = threadIdx.x; i < NV; i += 512) sh_lse[i] = g_rowlse[b * NV + i];
    __syncthreads();

    const int lane  = threadIdx.x & 31;
    const int chunk = (threadIdx.x >> 5) & 3;   // which v-chunk this warp covers
    const int sgrp  = threadIdx.x >> 7;         // which 128-column group
    const int col   = (sgrp << 7) + (lane << 2); // local column base (4 columns)
    const int v0    = chunk * VCHUNK;

    const float4* p = reinterpret_cast<const float4*>(
        x + (size_t)b * NV * NS + (size_t)v0 * NS + sbase + col);

    float se0 = 0.f, se1 = 0.f, se2 = 0.f, se3 = 0.f;
    float b0 = -3.4e38f, b1 = -3.4e38f, b2 = -3.4e38f, b3 = -3.4e38f;
    int   i0 = v0, i1 = v0, i2 = v0, i3 = v0;

#pragma unroll 8
    for (int i = 0; i < VCHUNK; i++) {
        float4 q = __ldg(p + (size_t)i * (NS / 4));
        float lse = sh_lse[v0 + i];
        se0 += __expf(q.x);
        se1 += __expf(q.y);
        se2 += __expf(q.z);
        se3 += __expf(q.w);
        float a;
        a = q.x - lse; if (a > b0) { b0 = a; i0 = v0 + i; }
        a = q.y - lse; if (a > b1) { b1 = a; i1 = v0 + i; }
        a = q.z - lse; if (a > b2) { b2 = a; i2 = v0 + i; }
        a = q.w - lse; if (a > b3) { b3 = a; i3 = v0 + i; }
    }

    p_sum [chunk][col + 0] = se0;  p_sum [chunk][col + 1] = se1;
    p_sum [chunk][col + 2] = se2;  p_sum [chunk][col + 3] = se3;
    p_best[chunk][col + 0] = b0;   p_best[chunk][col + 1] = b1;
    p_best[chunk][col + 2] = b2;   p_best[chunk][col + 3] = b3;
    p_pred[chunk][col + 0] = i0;   p_pred[chunk][col + 1] = i1;
    p_pred[chunk][col + 2] = i2;   p_pred[chunk][col + 3] = i3;
    __syncthreads();

    // ---- combine: one thread per column ----
    const int t = threadIdx.x;
    const int s = sbase + t;

    float sumexp = p_sum[0][t] + p_sum[1][t] + p_sum[2][t] + p_sum[3][t];
    float best = p_best[0][t];
    int   pred = p_pred[0][t];
#pragma unroll
    for (int c = 1; c < 4; c++) {
        float bc = p_best[c][t];
        if (bc > best) { best = bc; pred = p_pred[c][t]; }  // chunk order = v order
    }

    const int   tgt  = __ldg(target + b * NS + s);
    const float tval = __ldg(x + (size_t)b * NV * NS + (size_t)tgt * NS + s);
    float nll = __logf(sumexp) - tval;

    // penalty mask
    int pt = __ldg(tt + pred), qt = __ldg(tt + tgt);
    float w;
    if (pt != qt) {
        w = __ldg(coeff + 0);
    } else {
        float d = fabsf(__ldg(tvv + pred) - __ldg(tvv + tgt));  // integer-valued -> exact cmp
        if (pt == 0) {
            w = (d == 7.f) ? __ldg(harm + 0)
              : (d == 5.f) ? __ldg(harm + 1)
              : (d == 3.f) ? __ldg(harm + 2)
              : (d == 4.f) ? __ldg(harm + 3)
              : (d == 1.f) ? __ldg(harm + 4)
              : (d == 2.f) ? __ldg(harm + 5)
              :              __ldg(harm + 6);
        } else if (pt == 1) {
            w = __ldg(coeff + 1) * d * (1.f / 160.f);
        } else if (pt == 2) {
            w = __ldg(coeff + 2) * d * (1.f / 100.f);
        } else {
            w = __ldg(coeff + 3) * d * (1.f / 128.f);
        }
    }

    // deterministic block reduce
#pragma unroll
    for (int o = 16; o > 0; o >>= 1) {
        nll += __shfl_down_sync(0xffffffffu, nll, o);
        w   += __shfl_down_sync(0xffffffffu, w,   o);
    }
    __shared__ float rn[16], rw[16];
    int wid = threadIdx.x >> 5;
    if ((threadIdx.x & 31) == 0) { rn[wid] = nll; rw[wid] = w; }
    __syncthreads();
    if (threadIdx.x == 0) {
        float an = 0.f, aw = 0.f;
#pragma unroll
        for (int i = 0; i < 16; i++) { an += rn[i]; aw += rw[i]; }
        g_part[blockIdx.x] = make_float2(an, aw);
    }
}

// ---------------------------------------------------------------------------
// Pass 3: fold 128 partials into the final scalar.
// ---------------------------------------------------------------------------
__global__ void __launch_bounds__(128) k_final(float* __restrict__ out) {
    float2 v = g_part[threadIdx.x];
    float a = v.x, w = v.y;
#pragma unroll
    for (int o = 16; o > 0; o >>= 1) {
        a += __shfl_down_sync(0xffffffffu, a, o);
        w += __shfl_down_sync(0xffffffffu, w, o);
    }
    __shared__ float ra[4], rw2[4];
    if ((threadIdx.x & 31) == 0) { ra[threadIdx.x >> 5] = a; rw2[threadIdx.x >> 5] = w; }
    __syncthreads();
    if (threadIdx.x == 0) {
        float ta = ra[0] + ra[1] + ra[2] + ra[3];
        float tw = rw2[0] + rw2[1] + rw2[2] + rw2[3];
        const float inv = 1.f / (float)(NB * NS);
        float loss = ta * inv;
        out[0] = loss * (1.f + tw * inv);
    }
}

extern "C" void kernel_launch(void* const* d_in, const int* in_sizes, int n_in,
                              void* d_out, int out_size) {
    const float* x      = (const float*)d_in[0];
    const int*   target = (const int*)  d_in[1];
    const int*   tt     = (const int*)  d_in[2];
    const float* tv     = (const float*)d_in[3];
    const float* coeff  = (const float*)d_in[4];
    const float* harm   = (const float*)d_in[5];

    k_rowlse<<<NB * NV, 256>>>(x);
    k_cols<<<P2_BLOCKS, 512>>>(x, target, tt, tv, coeff, harm);
    k_final<<<1, 128>>>((float*)d_out);
}